// round 7
// baseline (speedup 1.0000x reference)
#include <cuda_runtime.h>
#include <cuda_fp16.h>

#define N_NODES 100000
#define N_EDGES_MAX 1600000
#define IN_F    256
#define HID_F   128
#define OUT_F   32

// Scratch: __device__ globals (no allocation allowed anywhere).
__device__ __half g_h0h[(size_t)N_NODES * HID_F];  // x @ W1   (fp16 payload)
__device__ float  g_h1[(size_t)N_NODES * HID_F];   // spmm1 out (fp32)
__device__ __half g_h2h[(size_t)N_NODES * OUT_F];  // relu(h1) @ W2 (fp16 payload)

// CSR scratch
__device__ int       g_counts[N_NODES];
__device__ int       g_row_ptr[N_NODES + 1];
__device__ int       g_cursor[N_NODES];
__device__ long long g_edges[N_EDGES_MAX];   // packed: low32=col, high32=val bits

// ---------------------------------------------------------------------------
// CSR build
// ---------------------------------------------------------------------------
__global__ void zero_counts_kernel() {
    int i = blockIdx.x * blockDim.x + threadIdx.x;
    if (i < N_NODES) g_counts[i] = 0;
}

__global__ void hist_kernel(const int* __restrict__ rows, int nE) {
    int i = blockIdx.x * blockDim.x + threadIdx.x;
    int base = i * 4;
    if (base + 4 <= nE) {
        int4 r4 = *(const int4*)(rows + base);
        atomicAdd(&g_counts[r4.x], 1);
        atomicAdd(&g_counts[r4.y], 1);
        atomicAdd(&g_counts[r4.z], 1);
        atomicAdd(&g_counts[r4.w], 1);
    } else {
        for (int e = base; e < nE; e++) atomicAdd(&g_counts[rows[e]], 1);
    }
}

#define SCAN_T 1024
__global__ __launch_bounds__(SCAN_T) void scan_kernel() {
    __shared__ int sums[SCAN_T];
    const int t = threadIdx.x;
    const int CHUNK = (N_NODES + SCAN_T - 1) / SCAN_T;  // 98
    const int s0 = t * CHUNK;
    const int s1 = min(s0 + CHUNK, N_NODES);

    int local = 0;
    for (int i = s0; i < s1; i++) local += g_counts[i];
    sums[t] = local;
    __syncthreads();

    for (int off = 1; off < SCAN_T; off <<= 1) {
        int v = (t >= off) ? sums[t - off] : 0;
        __syncthreads();
        sums[t] += v;
        __syncthreads();
    }
    int offset = sums[t] - local;

    int running = offset;
    for (int i = s0; i < s1; i++) {
        g_row_ptr[i] = running;
        g_cursor[i]  = running;
        running += g_counts[i];
    }
    if (s0 < N_NODES && s1 == N_NODES) g_row_ptr[N_NODES] = running;
}

__global__ void scatter_kernel(const int* __restrict__ rows,
                               const int* __restrict__ cols,
                               const float* __restrict__ vals,
                               int nE) {
    int e = blockIdx.x * blockDim.x + threadIdx.x;
    if (e >= nE) return;
    int r = rows[e];
    int pos = atomicAdd(&g_cursor[r], 1);
    long long pk = ((long long)__float_as_int(vals[e]) << 32) | (unsigned int)cols[e];
    g_edges[pos] = pk;
}

// ---------------------------------------------------------------------------
// GEMM1 (tf32 tensor): h0[M,128] = x[M,256] @ W1[256,128], fp16 store.
// ---------------------------------------------------------------------------
__device__ __forceinline__ unsigned f2tf32(float f) {
    unsigned u;
    asm("cvt.rna.tf32.f32 %0, %1;" : "=r"(u) : "f"(f));
    return u;
}

__global__ __launch_bounds__(256) void gemm1_tf32_kernel(const float* __restrict__ X,
                                                         const float* __restrict__ W1) {
    __shared__ unsigned As[128][36];
    __shared__ unsigned Bs[32][132];

    const int tid  = threadIdx.x;
    const int lane = tid & 31;
    const int warp = tid >> 5;
    const int warpM = warp >> 2;
    const int warpN = warp & 3;
    const int gid = lane >> 2;
    const int tig = lane & 3;
    const int m0 = blockIdx.x * 128;

    float acc[4][4][4];
#pragma unroll
    for (int a = 0; a < 4; a++)
#pragma unroll
        for (int b = 0; b < 4; b++)
#pragma unroll
            for (int c = 0; c < 4; c++) acc[a][b][c] = 0.f;

    for (int kc = 0; kc < IN_F; kc += 32) {
#pragma unroll
        for (int i = tid; i < 1024; i += 256) {
            int r  = i >> 3;
            int c4 = (i & 7) * 4;
            int gm = m0 + r;
            float4 v = make_float4(0.f, 0.f, 0.f, 0.f);
            if (gm < N_NODES)
                v = *(const float4*)(X + (size_t)gm * IN_F + kc + c4);
            As[r][c4 + 0] = f2tf32(v.x);
            As[r][c4 + 1] = f2tf32(v.y);
            As[r][c4 + 2] = f2tf32(v.z);
            As[r][c4 + 3] = f2tf32(v.w);
        }
#pragma unroll
        for (int i = tid; i < 1024; i += 256) {
            int r  = i >> 5;
            int c4 = (i & 31) * 4;
            float4 v = *(const float4*)(W1 + (size_t)(kc + r) * HID_F + c4);
            Bs[r][c4 + 0] = f2tf32(v.x);
            Bs[r][c4 + 1] = f2tf32(v.y);
            Bs[r][c4 + 2] = f2tf32(v.z);
            Bs[r][c4 + 3] = f2tf32(v.w);
        }
        __syncthreads();

#pragma unroll
        for (int ks = 0; ks < 4; ks++) {
            const int k = ks * 8;
            unsigned afrag[4][4];
#pragma unroll
            for (int mt = 0; mt < 4; mt++) {
                int rm = warpM * 64 + mt * 16;
                afrag[mt][0] = As[rm + gid][k + tig];
                afrag[mt][1] = As[rm + gid + 8][k + tig];
                afrag[mt][2] = As[rm + gid][k + tig + 4];
                afrag[mt][3] = As[rm + gid + 8][k + tig + 4];
            }
            unsigned bfrag[4][2];
#pragma unroll
            for (int nt = 0; nt < 4; nt++) {
                int nb = warpN * 32 + nt * 8;
                bfrag[nt][0] = Bs[k + tig][nb + gid];
                bfrag[nt][1] = Bs[k + tig + 4][nb + gid];
            }
#pragma unroll
            for (int mt = 0; mt < 4; mt++)
#pragma unroll
                for (int nt = 0; nt < 4; nt++) {
                    asm volatile(
                        "mma.sync.aligned.m16n8k8.row.col.f32.tf32.tf32.f32 "
                        "{%0,%1,%2,%3}, {%4,%5,%6,%7}, {%8,%9}, {%0,%1,%2,%3};"
                        : "+f"(acc[mt][nt][0]), "+f"(acc[mt][nt][1]),
                          "+f"(acc[mt][nt][2]), "+f"(acc[mt][nt][3])
                        : "r"(afrag[mt][0]), "r"(afrag[mt][1]),
                          "r"(afrag[mt][2]), "r"(afrag[mt][3]),
                          "r"(bfrag[nt][0]), "r"(bfrag[nt][1]));
                }
        }
        __syncthreads();
    }

#pragma unroll
    for (int mt = 0; mt < 4; mt++) {
#pragma unroll
        for (int nt = 0; nt < 4; nt++) {
            int col = warpN * 32 + nt * 8 + 2 * tig;
            int r0 = m0 + warpM * 64 + mt * 16 + gid;
            int r1 = r0 + 8;
            if (r0 < N_NODES) {
                __half2 h = __floats2half2_rn(acc[mt][nt][0], acc[mt][nt][1]);
                *(__half2*)(g_h0h + (size_t)r0 * HID_F + col) = h;
            }
            if (r1 < N_NODES) {
                __half2 h = __floats2half2_rn(acc[mt][nt][2], acc[mt][nt][3]);
                *(__half2*)(g_h0h + (size_t)r1 * HID_F + col) = h;
            }
        }
    }
}

// ---------------------------------------------------------------------------
// SpMM1 gather (F=128, fp16): warp per row; 16 lanes x uint4 per edge,
// two edges in flight per warp-iteration; cross-half shuffle reduce.
// ---------------------------------------------------------------------------
__device__ __forceinline__ void fma_h8(float acc[8], uint4 m, float v) {
    float2 f0 = __half22float2(*(__half2*)&m.x);
    float2 f1 = __half22float2(*(__half2*)&m.y);
    float2 f2 = __half22float2(*(__half2*)&m.z);
    float2 f3 = __half22float2(*(__half2*)&m.w);
    acc[0] = fmaf(f0.x, v, acc[0]);
    acc[1] = fmaf(f0.y, v, acc[1]);
    acc[2] = fmaf(f1.x, v, acc[2]);
    acc[3] = fmaf(f1.y, v, acc[3]);
    acc[4] = fmaf(f2.x, v, acc[4]);
    acc[5] = fmaf(f2.y, v, acc[5]);
    acc[6] = fmaf(f3.x, v, acc[6]);
    acc[7] = fmaf(f3.y, v, acc[7]);
}

__global__ __launch_bounds__(256) void spmm128_csr_kernel() {
    int row = blockIdx.x * 8 + (threadIdx.x >> 5);
    if (row >= N_NODES) return;
    int lane = threadIdx.x & 31;
    int h    = lane >> 4;      // edge slot within pair
    int sub  = lane & 15;      // 16B feature chunk (8 halves)

    int s  = __ldg(&g_row_ptr[row]);
    int e1 = __ldg(&g_row_ptr[row + 1]);

    float acc[8] = {0.f, 0.f, 0.f, 0.f, 0.f, 0.f, 0.f, 0.f};

    if (s < e1) {
        int e = s;
        // 4 edges in flight per iteration (2 per half-warp slot)
        for (; e + 4 <= e1; e += 4) {
            long long p0 = __ldg(&g_edges[e + h]);
            long long p1 = __ldg(&g_edges[e + 2 + h]);
            unsigned c0 = (unsigned)(p0 & 0xffffffffLL);
            unsigned c1 = (unsigned)(p1 & 0xffffffffLL);
            uint4 m0 = *((const uint4*)(g_h0h + (size_t)c0 * HID_F) + sub);
            uint4 m1 = *((const uint4*)(g_h0h + (size_t)c1 * HID_F) + sub);
            fma_h8(acc, m0, __int_as_float((int)(p0 >> 32)));
            fma_h8(acc, m1, __int_as_float((int)(p1 >> 32)));
        }
        // tail: clamped unconditional loads, zeroed val when invalid
        for (; e < e1; e += 2) {
            int ei = e + h;
            bool valid = ei < e1;
            int ec = valid ? ei : (e1 - 1);
            long long pk = __ldg(&g_edges[ec]);
            unsigned c = (unsigned)(pk & 0xffffffffLL);
            float v = valid ? __int_as_float((int)(pk >> 32)) : 0.f;
            uint4 m = *((const uint4*)(g_h0h + (size_t)c * HID_F) + sub);
            fma_h8(acc, m, v);
        }
    }

    // combine the two half-warp edge slots
#pragma unroll
    for (int j = 0; j < 8; j++)
        acc[j] += __shfl_xor_sync(0xffffffffu, acc[j], 16);

    // each lane writes 16B: features sub*8 + h*4 .. +3
    float4 w = h ? make_float4(acc[4], acc[5], acc[6], acc[7])
                 : make_float4(acc[0], acc[1], acc[2], acc[3]);
    *(float4*)(g_h1 + (size_t)row * HID_F + sub * 8 + h * 4) = w;
}

// ---------------------------------------------------------------------------
// GEMM2: g_h2h[M,32] = fp16( relu(g_h1)[M,128] @ W2[128,32] )
// ---------------------------------------------------------------------------
__global__ __launch_bounds__(256) void gemm2_kernel(const float* __restrict__ W2) {
    __shared__ float Ws[HID_F * OUT_F];
    for (int i = threadIdx.x; i < HID_F * OUT_F; i += 256) Ws[i] = W2[i];
    __syncthreads();

    int r = blockIdx.x * 256 + threadIdx.x;
    if (r >= N_NODES) return;

    float acc[OUT_F];
#pragma unroll
    for (int n = 0; n < OUT_F; n++) acc[n] = 0.f;

    const float4* hp = (const float4*)(g_h1 + (size_t)r * HID_F);
#pragma unroll 4
    for (int k4 = 0; k4 < HID_F / 4; k4++) {
        float4 h = hp[k4];
        h.x = fmaxf(h.x, 0.f);
        h.y = fmaxf(h.y, 0.f);
        h.z = fmaxf(h.z, 0.f);
        h.w = fmaxf(h.w, 0.f);
        int k = k4 * 4;
        float hh[4] = {h.x, h.y, h.z, h.w};
#pragma unroll
        for (int dk = 0; dk < 4; dk++) {
#pragma unroll
            for (int n = 0; n < OUT_F; n += 4) {
                float4 w = *(const float4*)&Ws[(k + dk) * OUT_F + n];
                acc[n + 0] = fmaf(hh[dk], w.x, acc[n + 0]);
                acc[n + 1] = fmaf(hh[dk], w.y, acc[n + 1]);
                acc[n + 2] = fmaf(hh[dk], w.z, acc[n + 2]);
                acc[n + 3] = fmaf(hh[dk], w.w, acc[n + 3]);
            }
        }
    }

    __half2 hb[OUT_F / 2];
#pragma unroll
    for (int n = 0; n < OUT_F / 2; n++)
        hb[n] = __floats2half2_rn(acc[2 * n], acc[2 * n + 1]);
    uint4* op = (uint4*)(g_h2h + (size_t)r * OUT_F);
#pragma unroll
    for (int q = 0; q < 4; q++)
        op[q] = ((uint4*)hb)[q];
}

// ---------------------------------------------------------------------------
// SpMM2 gather (F=32, fp16): warp per row; 4 lanes x uint4 per edge,
// 8 edges per warp-iteration; cross-group shuffle reduce.
// ---------------------------------------------------------------------------
__global__ __launch_bounds__(256) void spmm32_csr_kernel(float* __restrict__ out) {
    int row = blockIdx.x * 8 + (threadIdx.x >> 5);
    if (row >= N_NODES) return;
    int lane = threadIdx.x & 31;
    int g    = lane >> 2;      // edge slot 0..7
    int sub  = lane & 3;       // 16B feature chunk (8 halves)

    int s  = __ldg(&g_row_ptr[row]);
    int e1 = __ldg(&g_row_ptr[row + 1]);

    float acc[8] = {0.f, 0.f, 0.f, 0.f, 0.f, 0.f, 0.f, 0.f};

    if (s < e1) {
        for (int e = s; e < e1; e += 8) {
            int ei = e + g;
            bool valid = ei < e1;
            int ec = valid ? ei : (e1 - 1);
            long long pk = __ldg(&g_edges[ec]);
            unsigned c = (unsigned)(pk & 0xffffffffLL);
            float v = valid ? __int_as_float((int)(pk >> 32)) : 0.f;
            uint4 m = *((const uint4*)(g_h2h + (size_t)c * OUT_F) + sub);
            fma_h8(acc, m, v);
        }
    }

    // reduce across the 8 edge slots (xor 4, 8, 16)
#pragma unroll
    for (int off = 4; off < 32; off <<= 1)
#pragma unroll
        for (int j = 0; j < 8; j++)
            acc[j] += __shfl_xor_sync(0xffffffffu, acc[j], off);

    // lanes with g<2 write: feature base sub*8 + g*4 (8 lanes x 16B = 128B row)
    if (g < 2) {
        float4 w = g ? make_float4(acc[4], acc[5], acc[6], acc[7])
                     : make_float4(acc[0], acc[1], acc[2], acc[3]);
        *(float4*)(out + (size_t)row * OUT_F + sub * 8 + g * 4) = w;
    }
}

// ---------------------------------------------------------------------------
// Launch
// Inputs (metadata order): x, adj_rows, adj_cols, adj_vals, W1, W2
// ---------------------------------------------------------------------------
extern "C" void kernel_launch(void* const* d_in, const int* in_sizes, int n_in,
                              void* d_out, int out_size) {
    const float* x    = (const float*)d_in[0];
    const int*   rows = (const int*)d_in[1];
    const int*   cols = (const int*)d_in[2];
    const float* vals = (const float*)d_in[3];
    const float* W1   = (const float*)d_in[4];
    const float* W2   = (const float*)d_in[5];
    float* out = (float*)d_out;

    const int nE = in_sizes[1];

    // --- CSR build ---
    zero_counts_kernel<<<(N_NODES + 255) / 256, 256>>>();
    hist_kernel<<<(nE / 4 + 255) / 256, 256>>>(rows, nE);
    scan_kernel<<<1, SCAN_T>>>();
    scatter_kernel<<<(nE + 255) / 256, 256>>>(rows, cols, vals, nE);

    // GEMM1 (tf32 tensor): x @ W1 -> h0 (fp16 store)
    gemm1_tf32_kernel<<<(N_NODES + 127) / 128, 256>>>(x, W1);

    // SpMM1: h1 = A_hat @ h0  (fp16 gather, fp32 accum)
    spmm128_csr_kernel<<<(N_NODES + 7) / 8, 256>>>();

    // GEMM2: h2 = relu(h1) @ W2 (fp16 store)
    gemm2_kernel<<<(N_NODES + 255) / 256, 256>>>(W2);

    // SpMM2: out = A_hat @ h2  (fp16 gather, fp32 accum)
    spmm32_csr_kernel<<<(N_NODES + 7) / 8, 256>>>(out);
}

// round 8
// speedup vs baseline: 1.0549x; 1.0549x over previous
#include <cuda_runtime.h>
#include <cuda_fp16.h>

#define N_NODES 100000
#define N_EDGES_MAX 1600000
#define IN_F    256
#define HID_F   128
#define OUT_F   32

// Scratch: __device__ globals (no allocation allowed anywhere).
__device__ __half g_h0h[(size_t)N_NODES * HID_F];  // x @ W1   (fp16 payload)
__device__ float  g_h1[(size_t)N_NODES * HID_F];   // spmm1 out (fp32)
__device__ __half g_h2h[(size_t)N_NODES * OUT_F];  // relu(h1) @ W2 (fp16 payload)

// CSR scratch
__device__ int       g_counts[N_NODES];
__device__ int       g_row_ptr[N_NODES + 1];
__device__ int       g_cursor[N_NODES];
__device__ long long g_edges[N_EDGES_MAX];   // packed: low32=col, high32=val bits

// ---------------------------------------------------------------------------
// CSR build
// ---------------------------------------------------------------------------
__global__ void zero_counts_kernel() {
    int i = blockIdx.x * blockDim.x + threadIdx.x;
    if (i < N_NODES) g_counts[i] = 0;
}

__global__ void hist_kernel(const int* __restrict__ rows, int nE) {
    int i = blockIdx.x * blockDim.x + threadIdx.x;
    int base = i * 4;
    if (base + 4 <= nE) {
        int4 r4 = *(const int4*)(rows + base);
        atomicAdd(&g_counts[r4.x], 1);
        atomicAdd(&g_counts[r4.y], 1);
        atomicAdd(&g_counts[r4.z], 1);
        atomicAdd(&g_counts[r4.w], 1);
    } else {
        for (int e = base; e < nE; e++) atomicAdd(&g_counts[rows[e]], 1);
    }
}

#define SCAN_T 1024
__global__ __launch_bounds__(SCAN_T) void scan_kernel() {
    __shared__ int sums[SCAN_T];
    const int t = threadIdx.x;
    const int CHUNK = (N_NODES + SCAN_T - 1) / SCAN_T;  // 98
    const int s0 = t * CHUNK;
    const int s1 = min(s0 + CHUNK, N_NODES);

    int local = 0;
    for (int i = s0; i < s1; i++) local += g_counts[i];
    sums[t] = local;
    __syncthreads();

    for (int off = 1; off < SCAN_T; off <<= 1) {
        int v = (t >= off) ? sums[t - off] : 0;
        __syncthreads();
        sums[t] += v;
        __syncthreads();
    }
    int offset = sums[t] - local;

    int running = offset;
    for (int i = s0; i < s1; i++) {
        g_row_ptr[i] = running;
        g_cursor[i]  = running;
        running += g_counts[i];
    }
    if (s0 < N_NODES && s1 == N_NODES) g_row_ptr[N_NODES] = running;
}

__global__ void scatter_kernel(const int* __restrict__ rows,
                               const int* __restrict__ cols,
                               const float* __restrict__ vals,
                               int nE) {
    int e = blockIdx.x * blockDim.x + threadIdx.x;
    if (e >= nE) return;
    int r = rows[e];
    int pos = atomicAdd(&g_cursor[r], 1);
    long long pk = ((long long)__float_as_int(vals[e]) << 32) | (unsigned int)cols[e];
    g_edges[pos] = pk;
}

// ---------------------------------------------------------------------------
// GEMM1 (fp16 tensor, m16n8k16): h0[M,128] = x[M,256] @ W1[256,128].
// Block 128x128, K-chunks of 32. 8 warps; warp tile 64x32.
// A in smem row-major halves; B in smem TRANSPOSED Bt[n][k] halves.
// Pad 40 halves/row -> all fragment loads bank-conflict-free.
// ---------------------------------------------------------------------------
__global__ __launch_bounds__(256) void gemm1_fp16_kernel(const float* __restrict__ X,
                                                         const float* __restrict__ W1) {
    __shared__ __half As[128][40];   // As[m][k]
    __shared__ __half Bt[128][40];   // Bt[n][k]

    const int tid  = threadIdx.x;
    const int lane = tid & 31;
    const int warp = tid >> 5;
    const int warpM = warp >> 2;       // 0..1
    const int warpN = warp & 3;        // 0..3
    const int gid = lane >> 2;         // 0..7
    const int tig = lane & 3;          // 0..3
    const int m0 = blockIdx.x * 128;

    float acc[4][4][4];
#pragma unroll
    for (int a = 0; a < 4; a++)
#pragma unroll
        for (int b = 0; b < 4; b++)
#pragma unroll
            for (int c = 0; c < 4; c++) acc[a][b][c] = 0.f;

    for (int kc = 0; kc < IN_F; kc += 32) {
        // Fill As: 128 rows x 32 k = 1024 float4-sized items (4 floats each).
#pragma unroll
        for (int i = tid; i < 1024; i += 256) {
            int r  = i >> 3;           // 0..127
            int c4 = (i & 7) * 4;      // 0..28
            int gm = m0 + r;
            float4 v = make_float4(0.f, 0.f, 0.f, 0.f);
            if (gm < N_NODES)
                v = *(const float4*)(X + (size_t)gm * IN_F + kc + c4);
            __half2 h0 = __floats2half2_rn(v.x, v.y);
            __half2 h1 = __floats2half2_rn(v.z, v.w);
            uint2 pk;
            pk.x = *(unsigned*)&h0;
            pk.y = *(unsigned*)&h1;
            *(uint2*)&As[r][c4] = pk;
        }
        // Fill Bt[n][k]: per item, 4 k-values for one n. Loads coalesced in n.
#pragma unroll
        for (int i = tid; i < 1024; i += 256) {
            int n  = i & 127;
            int k4 = (i >> 7) * 4;     // 0..28
            float f0 = W1[(size_t)(kc + k4 + 0) * HID_F + n];
            float f1 = W1[(size_t)(kc + k4 + 1) * HID_F + n];
            float f2 = W1[(size_t)(kc + k4 + 2) * HID_F + n];
            float f3 = W1[(size_t)(kc + k4 + 3) * HID_F + n];
            __half2 h0 = __floats2half2_rn(f0, f1);
            __half2 h1 = __floats2half2_rn(f2, f3);
            uint2 pk;
            pk.x = *(unsigned*)&h0;
            pk.y = *(unsigned*)&h1;
            *(uint2*)&Bt[n][k4] = pk;
        }
        __syncthreads();

#pragma unroll
        for (int ks = 0; ks < 2; ks++) {
            const int k = ks * 16;
            unsigned afrag[4][4];
#pragma unroll
            for (int mt = 0; mt < 4; mt++) {
                int rm = warpM * 64 + mt * 16;
                afrag[mt][0] = *(unsigned*)&As[rm + gid][k + 2 * tig];
                afrag[mt][1] = *(unsigned*)&As[rm + gid + 8][k + 2 * tig];
                afrag[mt][2] = *(unsigned*)&As[rm + gid][k + 2 * tig + 8];
                afrag[mt][3] = *(unsigned*)&As[rm + gid + 8][k + 2 * tig + 8];
            }
            unsigned bfrag[4][2];
#pragma unroll
            for (int nt = 0; nt < 4; nt++) {
                int nb = warpN * 32 + nt * 8 + gid;
                bfrag[nt][0] = *(unsigned*)&Bt[nb][k + 2 * tig];
                bfrag[nt][1] = *(unsigned*)&Bt[nb][k + 2 * tig + 8];
            }
#pragma unroll
            for (int mt = 0; mt < 4; mt++)
#pragma unroll
                for (int nt = 0; nt < 4; nt++) {
                    asm volatile(
                        "mma.sync.aligned.m16n8k16.row.col.f32.f16.f16.f32 "
                        "{%0,%1,%2,%3}, {%4,%5,%6,%7}, {%8,%9}, {%0,%1,%2,%3};"
                        : "+f"(acc[mt][nt][0]), "+f"(acc[mt][nt][1]),
                          "+f"(acc[mt][nt][2]), "+f"(acc[mt][nt][3])
                        : "r"(afrag[mt][0]), "r"(afrag[mt][1]),
                          "r"(afrag[mt][2]), "r"(afrag[mt][3]),
                          "r"(bfrag[nt][0]), "r"(bfrag[nt][1]));
                }
        }
        __syncthreads();
    }

    // Epilogue: c0=(gid,2tig), c1=(gid,2tig+1), c2/3=(gid+8, same cols)
#pragma unroll
    for (int mt = 0; mt < 4; mt++) {
#pragma unroll
        for (int nt = 0; nt < 4; nt++) {
            int col = warpN * 32 + nt * 8 + 2 * tig;
            int r0 = m0 + warpM * 64 + mt * 16 + gid;
            int r1 = r0 + 8;
            if (r0 < N_NODES) {
                __half2 h = __floats2half2_rn(acc[mt][nt][0], acc[mt][nt][1]);
                *(__half2*)(g_h0h + (size_t)r0 * HID_F + col) = h;
            }
            if (r1 < N_NODES) {
                __half2 h = __floats2half2_rn(acc[mt][nt][2], acc[mt][nt][3]);
                *(__half2*)(g_h0h + (size_t)r1 * HID_F + col) = h;
            }
        }
    }
}

// ---------------------------------------------------------------------------
// SpMM1 gather (F=128, fp16 payload): h1[r] = sum_e val[e] * h0[col[e]]
// Warp per row; lane reads 4 halves (uint2); fp32 accumulate; 4-way unroll.
// (R6 form — best measured.)
// ---------------------------------------------------------------------------
__device__ __forceinline__ void fma_h4(float4& acc, uint2 m, float v) {
    float2 f0 = __half22float2(*(__half2*)&m.x);
    float2 f1 = __half22float2(*(__half2*)&m.y);
    acc.x = fmaf(f0.x, v, acc.x);
    acc.y = fmaf(f0.y, v, acc.y);
    acc.z = fmaf(f1.x, v, acc.z);
    acc.w = fmaf(f1.y, v, acc.w);
}

__global__ __launch_bounds__(256) void spmm128_csr_kernel() {
    int row = blockIdx.x * 8 + (threadIdx.x >> 5);
    if (row >= N_NODES) return;
    int lane = threadIdx.x & 31;

    int e  = __ldg(&g_row_ptr[row]);
    int e1 = __ldg(&g_row_ptr[row + 1]);

    float4 acc = make_float4(0.f, 0.f, 0.f, 0.f);

    for (; e + 4 <= e1; e += 4) {
        long long p0 = __ldg(&g_edges[e + 0]);
        long long p1 = __ldg(&g_edges[e + 1]);
        long long p2 = __ldg(&g_edges[e + 2]);
        long long p3 = __ldg(&g_edges[e + 3]);
        uint2 m0 = *((const uint2*)(g_h0h + (size_t)(unsigned int)(p0 & 0xffffffffLL) * HID_F) + lane);
        uint2 m1 = *((const uint2*)(g_h0h + (size_t)(unsigned int)(p1 & 0xffffffffLL) * HID_F) + lane);
        uint2 m2 = *((const uint2*)(g_h0h + (size_t)(unsigned int)(p2 & 0xffffffffLL) * HID_F) + lane);
        uint2 m3 = *((const uint2*)(g_h0h + (size_t)(unsigned int)(p3 & 0xffffffffLL) * HID_F) + lane);
        fma_h4(acc, m0, __int_as_float((int)(p0 >> 32)));
        fma_h4(acc, m1, __int_as_float((int)(p1 >> 32)));
        fma_h4(acc, m2, __int_as_float((int)(p2 >> 32)));
        fma_h4(acc, m3, __int_as_float((int)(p3 >> 32)));
    }
    for (; e < e1; e++) {
        long long pk = __ldg(&g_edges[e]);
        int c  = (int)(unsigned int)(pk & 0xffffffffLL);
        uint2 m = *((const uint2*)(g_h0h + (size_t)c * HID_F) + lane);
        fma_h4(acc, m, __int_as_float((int)(pk >> 32)));
    }
    *((float4*)(g_h1 + (size_t)row * HID_F) + lane) = acc;
}

// ---------------------------------------------------------------------------
// GEMM2: g_h2h[M,32] = fp16( relu(g_h1)[M,128] @ W2[128,32] )
// ---------------------------------------------------------------------------
__global__ __launch_bounds__(256) void gemm2_kernel(const float* __restrict__ W2) {
    __shared__ float Ws[HID_F * OUT_F];
    for (int i = threadIdx.x; i < HID_F * OUT_F; i += 256) Ws[i] = W2[i];
    __syncthreads();

    int r = blockIdx.x * 256 + threadIdx.x;
    if (r >= N_NODES) return;

    float acc[OUT_F];
#pragma unroll
    for (int n = 0; n < OUT_F; n++) acc[n] = 0.f;

    const float4* hp = (const float4*)(g_h1 + (size_t)r * HID_F);
#pragma unroll 4
    for (int k4 = 0; k4 < HID_F / 4; k4++) {
        float4 h = hp[k4];
        h.x = fmaxf(h.x, 0.f);
        h.y = fmaxf(h.y, 0.f);
        h.z = fmaxf(h.z, 0.f);
        h.w = fmaxf(h.w, 0.f);
        int k = k4 * 4;
        float hh[4] = {h.x, h.y, h.z, h.w};
#pragma unroll
        for (int dk = 0; dk < 4; dk++) {
#pragma unroll
            for (int n = 0; n < OUT_F; n += 4) {
                float4 w = *(const float4*)&Ws[(k + dk) * OUT_F + n];
                acc[n + 0] = fmaf(hh[dk], w.x, acc[n + 0]);
                acc[n + 1] = fmaf(hh[dk], w.y, acc[n + 1]);
                acc[n + 2] = fmaf(hh[dk], w.z, acc[n + 2]);
                acc[n + 3] = fmaf(hh[dk], w.w, acc[n + 3]);
            }
        }
    }

    __half2 hb[OUT_F / 2];
#pragma unroll
    for (int n = 0; n < OUT_F / 2; n++)
        hb[n] = __floats2half2_rn(acc[2 * n], acc[2 * n + 1]);
    uint4* op = (uint4*)(g_h2h + (size_t)r * OUT_F);
#pragma unroll
    for (int q = 0; q < 4; q++)
        op[q] = ((uint4*)hb)[q];
}

// ---------------------------------------------------------------------------
// SpMM2 gather (F=32, fp16 payload): 8 lanes per row, 4-way unroll (R6 form).
// ---------------------------------------------------------------------------
__global__ __launch_bounds__(256) void spmm32_csr_kernel(float* __restrict__ out) {
    int row = blockIdx.x * 32 + (threadIdx.x >> 3);
    if (row >= N_NODES) return;
    int lane = threadIdx.x & 7;

    int e  = __ldg(&g_row_ptr[row]);
    int e1 = __ldg(&g_row_ptr[row + 1]);

    float4 acc = make_float4(0.f, 0.f, 0.f, 0.f);

    for (; e + 4 <= e1; e += 4) {
        long long p0 = __ldg(&g_edges[e + 0]);
        long long p1 = __ldg(&g_edges[e + 1]);
        long long p2 = __ldg(&g_edges[e + 2]);
        long long p3 = __ldg(&g_edges[e + 3]);
        uint2 m0 = *((const uint2*)(g_h2h + (size_t)(unsigned int)(p0 & 0xffffffffLL) * OUT_F) + lane);
        uint2 m1 = *((const uint2*)(g_h2h + (size_t)(unsigned int)(p1 & 0xffffffffLL) * OUT_F) + lane);
        uint2 m2 = *((const uint2*)(g_h2h + (size_t)(unsigned int)(p2 & 0xffffffffLL) * OUT_F) + lane);
        uint2 m3 = *((const uint2*)(g_h2h + (size_t)(unsigned int)(p3 & 0xffffffffLL) * OUT_F) + lane);
        fma_h4(acc, m0, __int_as_float((int)(p0 >> 32)));
        fma_h4(acc, m1, __int_as_float((int)(p1 >> 32)));
        fma_h4(acc, m2, __int_as_float((int)(p2 >> 32)));
        fma_h4(acc, m3, __int_as_float((int)(p3 >> 32)));
    }
    for (; e < e1; e++) {
        long long pk = __ldg(&g_edges[e]);
        int c  = (int)(unsigned int)(pk & 0xffffffffLL);
        uint2 m = *((const uint2*)(g_h2h + (size_t)c * OUT_F) + lane);
        fma_h4(acc, m, __int_as_float((int)(pk >> 32)));
    }
    *((float4*)(out + (size_t)row * OUT_F) + lane) = acc;
}

// ---------------------------------------------------------------------------
// Launch
// Inputs (metadata order): x, adj_rows, adj_cols, adj_vals, W1, W2
// ---------------------------------------------------------------------------
extern "C" void kernel_launch(void* const* d_in, const int* in_sizes, int n_in,
                              void* d_out, int out_size) {
    const float* x    = (const float*)d_in[0];
    const int*   rows = (const int*)d_in[1];
    const int*   cols = (const int*)d_in[2];
    const float* vals = (const float*)d_in[3];
    const float* W1   = (const float*)d_in[4];
    const float* W2   = (const float*)d_in[5];
    float* out = (float*)d_out;

    const int nE = in_sizes[1];

    // --- CSR build ---
    zero_counts_kernel<<<(N_NODES + 255) / 256, 256>>>();
    hist_kernel<<<(nE / 4 + 255) / 256, 256>>>(rows, nE);
    scan_kernel<<<1, SCAN_T>>>();
    scatter_kernel<<<(nE + 255) / 256, 256>>>(rows, cols, vals, nE);

    // GEMM1 (fp16 tensor): x @ W1 -> h0 (fp16 store)
    gemm1_fp16_kernel<<<(N_NODES + 127) / 128, 256>>>(x, W1);

    // SpMM1: h1 = A_hat @ h0  (fp16 gather, fp32 accum)
    spmm128_csr_kernel<<<(N_NODES + 7) / 8, 256>>>();

    // GEMM2: h2 = relu(h1) @ W2 (fp16 store)
    gemm2_kernel<<<(N_NODES + 255) / 256, 256>>>(W2);

    // SpMM2: out = A_hat @ h2  (fp16 gather, fp32 accum)
    spmm32_csr_kernel<<<(N_NODES + 31) / 32, 256>>>(out);
}